// round 17
// baseline (speedup 1.0000x reference)
#include <cuda_runtime.h>
#include <cuda_fp16.h>
#include <cstdint>

// ---------------------------------------------------------------------------
// RNN-T joint network (sm_103 legacy tensor path, fp16 mma everywhere):
//   YP = y@W_pr + b_pr   [400,256] fp32 (global)
//   XT tile = x@W_tr + b_tr  -> kept in SMEM, fused with:
//   Zh = fp16(tanh(XT + YP))  [160000,256]  (written directly)
//   out= Zh @ Wh + b_cls [160000,1024]  persistent fp16 mma (frozen R13 cfg)
// ---------------------------------------------------------------------------

#define B_  4
#define T_  400
#define U_  100
#define DTR 768
#define DPR 640
#define DJ  256
#define V_  1024
#define M_TOTAL (B_ * T_ * U_)   // 160000

__device__ float  g_YP[(size_t)B_ * U_ * DJ];
__device__ __half g_Zh[(size_t)M_TOTAL * DJ];    // 82 MB
__device__ __half g_Wh[(size_t)V_ * DJ];         // fp16(W_cls^T)  [V][DJ]
__device__ __half g_WtrT[(size_t)DJ * DTR];      // fp16(W_tr^T)   [256][768]
__device__ __half g_WprT[(size_t)DJ * DPR];      // fp16(W_pr^T)   [256][640]

__device__ __forceinline__ float fast_tanh(float x) {
    float r;
    asm("tanh.approx.f32 %0, %1;" : "=f"(r) : "f"(x));
    return r;
}

__device__ __forceinline__ void mma_f16(float* c, const uint32_t* a, const uint32_t* b) {
    asm volatile(
        "mma.sync.aligned.m16n8k16.row.col.f32.f16.f16.f32 "
        "{%0,%1,%2,%3}, {%4,%5,%6,%7}, {%8,%9}, {%0,%1,%2,%3};\n"
        : "+f"(c[0]), "+f"(c[1]), "+f"(c[2]), "+f"(c[3])
        : "r"(a[0]), "r"(a[1]), "r"(a[2]), "r"(a[3]), "r"(b[0]), "r"(b[1]));
}

__device__ __forceinline__ void ldsm_x4(uint32_t& r0, uint32_t& r1, uint32_t& r2,
                                        uint32_t& r3, uint32_t addr) {
    asm volatile("ldmatrix.sync.aligned.m8n8.x4.shared.b16 {%0,%1,%2,%3}, [%4];"
                 : "=r"(r0), "=r"(r1), "=r"(r2), "=r"(r3) : "r"(addr));
}

__device__ __forceinline__ void ldsm_x2(uint32_t& r0, uint32_t& r1, uint32_t addr) {
    asm volatile("ldmatrix.sync.aligned.m8n8.x2.shared.b16 {%0,%1}, [%2];"
                 : "=r"(r0), "=r"(r1) : "r"(addr));
}

__device__ __forceinline__ uint32_t smem_u32(const void* p) {
    uint32_t a;
    asm("{ .reg .u64 t; cvta.to.shared.u64 t, %1; cvt.u32.u64 %0, t; }" : "=r"(a) : "l"(p));
    return a;
}

// ---------------------------------------------------------------------------
// Stage 0 (merged): all three weight transposes+fp16 in one launch.
// ---------------------------------------------------------------------------
__global__ __launch_bounds__(256)
void prep_weights(const float* __restrict__ Wcls, const float* __restrict__ Wtr,
                  const float* __restrict__ Wpr, __half* __restrict__ Wh,
                  __half* __restrict__ WtrT, __half* __restrict__ WprT) {
    __shared__ float t[32][33];
    const int idx = blockIdx.x;
    const float* W;
    __half* D;
    int srcN, dstK, n0, k0;
    if (idx < 256) {
        W = Wcls; D = Wh; srcN = V_; dstK = DJ;
        n0 = (idx & 31) * 32; k0 = (idx >> 5) * 32;
    } else if (idx < 448) {
        int i = idx - 256;
        W = Wtr; D = WtrT; srcN = DJ; dstK = DTR;
        n0 = (i & 7) * 32; k0 = (i >> 3) * 32;
    } else {
        int i = idx - 448;
        W = Wpr; D = WprT; srcN = DJ; dstK = DPR;
        n0 = (i & 7) * 32; k0 = (i >> 3) * 32;
    }
    int tx = threadIdx.x, ty = threadIdx.y;   // (32, 8)
#pragma unroll
    for (int i = 0; i < 32; i += 8)
        t[ty + i][tx] = W[(size_t)(k0 + ty + i) * srcN + n0 + tx];
    __syncthreads();
#pragma unroll
    for (int i = 0; i < 32; i += 8)
        D[(size_t)(n0 + ty + i) * dstK + k0 + tx] = __float2half_rn(t[tx][ty + i]);
}

// ---------------------------------------------------------------------------
// Stage 1a: YP = y@W_pr + b_pr  (fp16 tensor, all-B prefetch, 16m x 32n)
// Grid 200: m-tile = blk>>3 (25), n-slice = blk&7.  K=640, 10 chunks.
// ---------------------------------------------------------------------------
#define YP_B_CH 4096
#define YP_A_CH 2048
#define YP_NCH 10
#define YP_SMEM (YP_NCH * (YP_B_CH + YP_A_CH))   // 61440

__global__ __launch_bounds__(128)
void yp_gemm_f16(const float* __restrict__ y, const __half* __restrict__ WprT,
                 const float* __restrict__ bpr, float* __restrict__ YP) {
    extern __shared__ char sm[];
    const uint32_t smbase = smem_u32(sm);
    const uint32_t abase = smbase + YP_NCH * YP_B_CH;

    const int bidx = blockIdx.x;
    const int n0 = (bidx & 7) * 32;
    const int m0 = (bidx >> 3) * 16;
    const int K = DPR;

    const int tid = threadIdx.x;
    const int lane = tid & 31, w = tid >> 5;
    const int gid = lane >> 2, tig = lane & 3;

    // B prefetch: thread t -> row t>>2 (0..31), chunks (t&3)*2, +1
    {
        const int b_row = tid >> 2;
        const int b_c0 = (tid & 3) * 2;
        const __half* b_src = WprT + (size_t)(n0 + b_row) * K;
        const uint32_t b_dst = smbase + (uint32_t)b_row * 128;
        const uint32_t brx = (uint32_t)(b_row & 7);
#pragma unroll
        for (int c = 0; c < YP_NCH; c++) {
#pragma unroll
            for (int i = 0; i < 2; i++) {
                uint32_t ch = (uint32_t)(b_c0 + i);
                asm volatile("cp.async.cg.shared.global [%0], [%1], 16;"
                             :: "r"(b_dst + (uint32_t)c * YP_B_CH + ((ch ^ brx) << 4)),
                                "l"(b_src + c * 64 + ch * 8));
            }
            asm volatile("cp.async.commit_group;" ::: "memory");
        }
    }
    // A convert: thread t -> row t>>3 (0..15), 16B chunk t&7
    {
        const int a_row = tid >> 3;
        const int a_ch = tid & 7;
        const float* a_srcp = y + (size_t)(m0 + a_row) * K + a_ch * 8;
        char* a_dstp = sm + (YP_NCH * YP_B_CH) + a_row * 128 +
                       (((uint32_t)a_ch ^ (uint32_t)(a_row & 7)) << 4);
#pragma unroll
        for (int c = 0; c < YP_NCH; c++) {
            float4 v0 = *(const float4*)(a_srcp + c * 64);
            float4 v1 = *(const float4*)(a_srcp + c * 64 + 4);
            __half2 h0 = __floats2half2_rn(v0.x, v0.y);
            __half2 h1 = __floats2half2_rn(v0.z, v0.w);
            __half2 h2 = __floats2half2_rn(v1.x, v1.y);
            __half2 h3 = __floats2half2_rn(v1.z, v1.w);
            uint4 pk;
            pk.x = *reinterpret_cast<uint32_t*>(&h0);
            pk.y = *reinterpret_cast<uint32_t*>(&h1);
            pk.z = *reinterpret_cast<uint32_t*>(&h2);
            pk.w = *reinterpret_cast<uint32_t*>(&h3);
            *reinterpret_cast<uint4*>(a_dstp + c * YP_A_CH) = pk;
        }
    }

    const int l8 = lane & 7, j = lane >> 3;
    const uint32_t rowlowA = (uint32_t)(((j & 1) << 3) + l8);
    const uint32_t cbitA = (uint32_t)(j >> 1);
    const uint32_t xorvA = (uint32_t)l8;
    const uint32_t aBase = abase + rowlowA * 128;
    const int l16 = lane & 15;
    const uint32_t jb = (uint32_t)(l16 >> 3);
    const uint32_t rowB = (uint32_t)(w * 8 + (l16 & 7));
    const uint32_t xorvB = (uint32_t)(l16 & 7);
    const uint32_t bBase = smbase + rowB * 128;

    float acc[4];
    acc[0] = acc[1] = acc[2] = acc[3] = 0.f;

#define YP_CHUNK(c) { \
        asm volatile("cp.async.wait_group %0;" :: "n"(YP_NCH - 1 - (c)) : "memory"); \
        __syncthreads(); \
        _Pragma("unroll") \
        for (int ks = 0; ks < 4; ks++) { \
            uint32_t a[4], b[2]; \
            ldsm_x4(a[0], a[1], a[2], a[3], \
                    aBase + (c) * YP_A_CH + \
                    ((((uint32_t)(ks << 1) + cbitA) ^ xorvA) << 4)); \
            ldsm_x2(b[0], b[1], \
                    bBase + (c) * YP_B_CH + \
                    ((((uint32_t)(ks << 1) + jb) ^ xorvB) << 4)); \
            mma_f16(acc, a, b); \
        } \
    }

    YP_CHUNK(0); YP_CHUNK(1); YP_CHUNK(2); YP_CHUNK(3); YP_CHUNK(4);
    YP_CHUNK(5); YP_CHUNK(6); YP_CHUNK(7); YP_CHUNK(8); YP_CHUNK(9);
#undef YP_CHUNK

    {
        int cidx = n0 + w * 8 + 2 * tig;
        float bv0 = __ldg(bpr + cidx);
        float bv1 = __ldg(bpr + cidx + 1);
        float* r0p = YP + (size_t)(m0 + gid) * DJ + cidx;
        float* r1p = YP + (size_t)(m0 + gid + 8) * DJ + cidx;
        r0p[0] = acc[0] + bv0;
        r0p[1] = acc[1] + bv1;
        r1p[0] = acc[2] + bv0;
        r1p[1] = acc[3] + bv1;
    }
}

// ---------------------------------------------------------------------------
// Stage 1b+2 (fused): XT tile (32m x 32n) via fp16 tensor GEMM -> SMEM,
// then Zh[bt, u, cols] = fp16(tanh(xt + YP[b,u,cols])) for all u.
// Grid 400: m-tile = blk>>3 (50 tiles of 32 bt rows), n-slice = blk&7.
// XT never touches global memory.
// ---------------------------------------------------------------------------
#define XT_B_CH 4096
#define XT_A_CH 4096
#define XT_NCH 12
#define XT_SMEM (XT_NCH * (XT_B_CH + XT_A_CH))   // 98304

__global__ __launch_bounds__(128)
void xt_z_f16(const float* __restrict__ x, const __half* __restrict__ WtrT,
              const float* __restrict__ btr, const float* __restrict__ YP,
              __half* __restrict__ Z) {
    extern __shared__ char sm[];
    __shared__ float xs[32][33];
    const uint32_t smbase = smem_u32(sm);
    const uint32_t abase = smbase + XT_NCH * XT_B_CH;

    const int bidx = blockIdx.x;
    const int n0 = (bidx & 7) * 32;
    const int m0 = (bidx >> 3) * 32;        // bt row base
    const int K = DTR;

    const int tid = threadIdx.x;
    const int lane = tid & 31, w = tid >> 5;
    const int gid = lane >> 2, tig = lane & 3;

    // B prefetch: thread t -> row t>>2 (0..31), chunks (t&3)*2, +1
    {
        const int b_row = tid >> 2;
        const int b_c0 = (tid & 3) * 2;
        const __half* b_src = WtrT + (size_t)(n0 + b_row) * K;
        const uint32_t b_dst = smbase + (uint32_t)b_row * 128;
        const uint32_t brx = (uint32_t)(b_row & 7);
#pragma unroll 4
        for (int c = 0; c < XT_NCH; c++) {
#pragma unroll
            for (int i = 0; i < 2; i++) {
                uint32_t ch = (uint32_t)(b_c0 + i);
                asm volatile("cp.async.cg.shared.global [%0], [%1], 16;"
                             :: "r"(b_dst + (uint32_t)c * XT_B_CH + ((ch ^ brx) << 4)),
                                "l"(b_src + c * 64 + ch * 8));
            }
            asm volatile("cp.async.commit_group;" ::: "memory");
        }
    }
    // A convert: thread t -> row t>>2 (0..31), chunks (t&3)*2, +1
    {
        const int a_row = tid >> 2;
        const int a_c0 = (tid & 3) * 2;
        const float* a_srcp = x + (size_t)(m0 + a_row) * K;
        char* a_dstp = sm + (XT_NCH * XT_B_CH) + a_row * 128;
        const uint32_t arx = (uint32_t)(a_row & 7);
#pragma unroll 4
        for (int c = 0; c < XT_NCH; c++) {
#pragma unroll
            for (int i = 0; i < 2; i++) {
                int ch = a_c0 + i;
                float4 v0 = *(const float4*)(a_srcp + c * 64 + ch * 8);
                float4 v1 = *(const float4*)(a_srcp + c * 64 + ch * 8 + 4);
                __half2 h0 = __floats2half2_rn(v0.x, v0.y);
                __half2 h1 = __floats2half2_rn(v0.z, v0.w);
                __half2 h2 = __floats2half2_rn(v1.x, v1.y);
                __half2 h3 = __floats2half2_rn(v1.z, v1.w);
                uint4 pk;
                pk.x = *reinterpret_cast<uint32_t*>(&h0);
                pk.y = *reinterpret_cast<uint32_t*>(&h1);
                pk.z = *reinterpret_cast<uint32_t*>(&h2);
                pk.w = *reinterpret_cast<uint32_t*>(&h3);
                *reinterpret_cast<uint4*>(
                    a_dstp + c * XT_A_CH + (((uint32_t)ch ^ arx) << 4)) = pk;
            }
        }
    }

    const int l8 = lane & 7, j = lane >> 3;
    const uint32_t rowlowA = (uint32_t)(((j & 1) << 3) + l8);
    const uint32_t cbitA = (uint32_t)(j >> 1);
    const uint32_t xorvA = (uint32_t)l8;
    const uint32_t aBase = abase + rowlowA * 128;
    const int l16 = lane & 15;
    const uint32_t jb = (uint32_t)(l16 >> 3);
    const uint32_t rowB = (uint32_t)(w * 8 + (l16 & 7));
    const uint32_t xorvB = (uint32_t)(l16 & 7);
    const uint32_t bBase = smbase + rowB * 128;

    float acc[2][4];
#pragma unroll
    for (int fm = 0; fm < 2; fm++)
#pragma unroll
        for (int r = 0; r < 4; r++) acc[fm][r] = 0.f;

#define XT_CHUNK(c) { \
        asm volatile("cp.async.wait_group %0;" :: "n"(XT_NCH - 1 - (c)) : "memory"); \
        __syncthreads(); \
        _Pragma("unroll") \
        for (int ks = 0; ks < 4; ks++) { \
            const uint32_t aCh = (((uint32_t)(ks << 1) + cbitA) ^ xorvA) << 4; \
            const uint32_t bCh = (((uint32_t)(ks << 1) + jb) ^ xorvB) << 4; \
            uint32_t a0[4], a1[4], b[2]; \
            ldsm_x4(a0[0], a0[1], a0[2], a0[3], aBase + (c) * XT_A_CH + aCh); \
            ldsm_x2(b[0], b[1], bBase + (c) * XT_B_CH + bCh); \
            mma_f16(acc[0], a0, b); \
            ldsm_x4(a1[0], a1[1], a1[2], a1[3], \
                    aBase + (c) * XT_A_CH + 16 * 128 + aCh); \
            mma_f16(acc[1], a1, b); \
        } \
    }

    XT_CHUNK(0);  XT_CHUNK(1);  XT_CHUNK(2);  XT_CHUNK(3);
    XT_CHUNK(4);  XT_CHUNK(5);  XT_CHUNK(6);  XT_CHUNK(7);
    XT_CHUNK(8);  XT_CHUNK(9);  XT_CHUNK(10); XT_CHUNK(11);
#undef XT_CHUNK

    // epilogue -> smem xs (XT values with bias), local rows 0..31, cols 0..31
    {
        int col = w * 8 + 2 * tig;
        float bv0 = __ldg(btr + n0 + col);
        float bv1 = __ldg(btr + n0 + col + 1);
#pragma unroll
        for (int fm = 0; fm < 2; fm++) {
            xs[fm * 16 + gid][col]         = acc[fm][0] + bv0;
            xs[fm * 16 + gid][col + 1]     = acc[fm][1] + bv1;
            xs[fm * 16 + gid + 8][col]     = acc[fm][2] + bv0;
            xs[fm * 16 + gid + 8][col + 1] = acc[fm][3] + bv1;
        }
    }
    __syncthreads();

    // expansion: thread t -> local row r = t>>2, col-octet q = t&3.
    {
        const int r = tid >> 2;
        const int q = tid & 3;
        const int bt = m0 + r;
        const int b = bt / T_;
        float xv[8];
#pragma unroll
        for (int i = 0; i < 8; i++) xv[i] = xs[r][q * 8 + i];

        const float* yb = YP + (size_t)b * U_ * DJ + n0 + q * 8;
        __half* zrow = Z + (size_t)bt * U_ * DJ + n0 + q * 8;

#pragma unroll 4
        for (int u = 0; u < U_; u++) {
            float4 y0 = *(const float4*)(yb + (size_t)u * DJ);
            float4 y1 = *(const float4*)(yb + (size_t)u * DJ + 4);
            __half2 h0 = __floats2half2_rn(fast_tanh(xv[0] + y0.x),
                                           fast_tanh(xv[1] + y0.y));
            __half2 h1 = __floats2half2_rn(fast_tanh(xv[2] + y0.z),
                                           fast_tanh(xv[3] + y0.w));
            __half2 h2 = __floats2half2_rn(fast_tanh(xv[4] + y1.x),
                                           fast_tanh(xv[5] + y1.y));
            __half2 h3 = __floats2half2_rn(fast_tanh(xv[6] + y1.z),
                                           fast_tanh(xv[7] + y1.w));
            uint4 pk;
            pk.x = *reinterpret_cast<uint32_t*>(&h0);
            pk.y = *reinterpret_cast<uint32_t*>(&h1);
            pk.z = *reinterpret_cast<uint32_t*>(&h2);
            pk.w = *reinterpret_cast<uint32_t*>(&h3);
            *reinterpret_cast<uint4*>(zrow + (size_t)u * DJ) = pk;
        }
    }
}

// ---------------------------------------------------------------------------
// Stage 3: out = Zh @ Wh^T + b_cls, persistent CTAs (frozen R13 config).
// ---------------------------------------------------------------------------
#define BM 128
#define BN 128
#define BKH 64
#define ROWB 128
#define A_STAGE_BYTES (BM * ROWB)               // 16384
#define NSTAGES 3
#define B_BYTES (BN * DJ * 2)                   // 65536
#define B_OFF (NSTAGES * A_STAGE_BYTES)         // 49152
#define JSMEM (B_OFF + B_BYTES)                 // 114688
#define NCHUNKS (DJ / BKH)                      // 4
#define MGROUPS 37
#define MTILES (M_TOTAL / BM)                   // 1250
#define NJCTAS (8 * MGROUPS)                    // 296

__global__ __launch_bounds__(128, 2)
void joint_gemm_f16(const __half* __restrict__ Z, const __half* __restrict__ Wh,
                    const float* __restrict__ bias, float* __restrict__ out) {
    extern __shared__ char sm[];
    const uint32_t smbase = smem_u32(sm);
    const uint32_t bbase = smbase + B_OFF;

    const int K = DJ;
    const int N = V_;

    const int n0 = (blockIdx.x & 7) * BN;
    const int mgroup = blockIdx.x >> 3;
    const int tid = threadIdx.x;
    const int lane = tid & 31, w = tid >> 5;
    const int warpM = w & 1, warpN = w >> 1;
    const int wm0 = warpM * 64, wn0 = warpN * 64;
    const int gid = lane >> 2, tig = lane & 3;

    const int l8 = lane & 7, j = lane >> 3;
    const uint32_t rowlow = (uint32_t)(((j & 1) << 3) + l8);
    const uint32_t cbit = (uint32_t)(j >> 1);
    const uint32_t xorv = (uint32_t)l8;
    const uint32_t aRow = ((uint32_t)wm0 + rowlow) * ROWB;
    const uint32_t bRow = bbase + ((uint32_t)wn0 + rowlow) * 512;

    float bv[8][2];
#pragma unroll
    for (int fn = 0; fn < 8; fn++) {
        int cidx = n0 + wn0 + fn * 8 + 2 * tig;
        bv[fn][0] = bias[cidx];
        bv[fn][1] = bias[cidx + 1];
    }

    {
        int r = tid;
        const __half* src = Wh + (size_t)(n0 + r) * K;
        uint32_t dbase = bbase + (uint32_t)r * 512;
        uint32_t rx = (uint32_t)(r & 7);
#pragma unroll
        for (int ch = 0; ch < 32; ch++) {
            uint32_t d = dbase + (((uint32_t)ch ^ rx) << 4);
            asm volatile("cp.async.cg.shared.global [%0], [%1], 16;"
                         :: "r"(d), "l"(src + ch * 8));
        }
        asm volatile("cp.async.commit_group;" ::: "memory");
    }

    const int lrow = tid >> 3;
    const int lchunk = tid & 7;

#define LOAD_A(mt, c, s) do { \
    uint32_t _sb = smbase + (uint32_t)(s) * A_STAGE_BYTES; \
    _Pragma("unroll") \
    for (int p = 0; p < 8; p++) { \
        int _r = lrow + p * 16; \
        uint32_t _d = _sb + (uint32_t)_r * ROWB + \
                      ((uint32_t)(lchunk ^ (_r & 7)) << 4); \
        const __half* _a = Z + (size_t)((mt) * BM + _r) * K + (c) * BKH + lchunk * 8; \
        asm volatile("cp.async.cg.shared.global [%0], [%1], 16;" \
                     :: "r"(_d), "l"(_a)); \
    } \
    asm volatile("cp.async.commit_group;" ::: "memory"); \
} while (0)

    int lt = mgroup;
    int lc = 0;
    int ls = 0;
#define ADV_LOAD() do { \
    if (++lc == NCHUNKS) { lc = 0; lt += MGROUPS; if (lt >= MTILES) lt = -1; } \
    ls = (ls + 1 == NSTAGES) ? 0 : ls + 1; \
} while (0)

    LOAD_A(lt, lc, ls); ADV_LOAD();
    LOAD_A(lt, lc, ls); ADV_LOAD();

    int cs = 0;

#pragma unroll 1
    for (int t = mgroup; t < MTILES; t += MGROUPS) {
        const int m0 = t * BM;
        const bool lastTile = (t + MGROUPS >= MTILES);

        float acc[4][8][4];
#pragma unroll
        for (int fm = 0; fm < 4; fm++)
#pragma unroll
            for (int fn = 0; fn < 8; fn++)
#pragma unroll
                for (int r = 0; r < 4; r++) acc[fm][fn][r] = 0.f;

#pragma unroll
        for (int c = 0; c < NCHUNKS; c++) {
            if (lastTile && c == NCHUNKS - 1)
                asm volatile("cp.async.wait_group 0;" ::: "memory");
            else
                asm volatile("cp.async.wait_group 1;" ::: "memory");
            __syncthreads();
            if (lt >= 0) { LOAD_A(lt, lc, ls); ADV_LOAD(); }

            const uint32_t aB = smbase + (uint32_t)cs * A_STAGE_BYTES + aRow;
            cs = (cs + 1 == NSTAGES) ? 0 : cs + 1;
#pragma unroll
            for (int ks = 0; ks < 4; ks++) {
                const uint32_t aCh = (((uint32_t)(ks << 1) + cbit) ^ xorv) << 4;
                const uint32_t bCh = (((uint32_t)(c * 8 + (ks << 1)) + cbit) ^ xorv) << 4;
                uint32_t a[4][4], b[8][2];
#pragma unroll
                for (int fm = 0; fm < 4; fm++)
                    ldsm_x4(a[fm][0], a[fm][1], a[fm][2], a[fm][3],
                            aB + (uint32_t)fm * (16 * ROWB) + aCh);
#pragma unroll
                for (int p = 0; p < 4; p++) {
                    uint32_t r0, r1, r2, r3;
                    ldsm_x4(r0, r1, r2, r3, bRow + (uint32_t)p * (16 * 512) + bCh);
                    b[2 * p][0] = r0;
                    b[2 * p + 1][0] = r1;
                    b[2 * p][1] = r2;
                    b[2 * p + 1][1] = r3;
                }
#pragma unroll
                for (int fm = 0; fm < 4; fm++)
#pragma unroll
                    for (int fn = 0; fn < 8; fn++) mma_f16(acc[fm][fn], a[fm], b[fn]);
            }
        }

#pragma unroll
        for (int fm = 0; fm < 4; fm++) {
            int r0 = m0 + wm0 + fm * 16 + gid;
#pragma unroll
            for (int fn = 0; fn < 8; fn++) {
                int cidx = n0 + wn0 + fn * 8 + 2 * tig;
                float2 v0 = make_float2(acc[fm][fn][0] + bv[fn][0],
                                        acc[fm][fn][1] + bv[fn][1]);
                float2 v1 = make_float2(acc[fm][fn][2] + bv[fn][0],
                                        acc[fm][fn][3] + bv[fn][1]);
                *(float2*)(out + (size_t)r0 * N + cidx) = v0;
                *(float2*)(out + (size_t)(r0 + 8) * N + cidx) = v1;
            }
        }
    }
#undef LOAD_A
#undef ADV_LOAD
}

// ---------------------------------------------------------------------------
extern "C" void kernel_launch(void* const* d_in, const int* in_sizes, int n_in,
                              void* d_out, int out_size) {
    const float* x     = (const float*)d_in[0];
    const float* y     = (const float*)d_in[1];
    const float* W_tr  = (const float*)d_in[2];
    const float* b_tr  = (const float*)d_in[3];
    const float* W_pr  = (const float*)d_in[4];
    const float* b_pr  = (const float*)d_in[5];
    const float* W_cls = (const float*)d_in[6];
    const float* b_cls = (const float*)d_in[7];
    float* out = (float*)d_out;

    void *pYP, *pZh, *pWh, *pWtrT, *pWprT;
    cudaGetSymbolAddress(&pYP, g_YP);
    cudaGetSymbolAddress(&pZh, g_Zh);
    cudaGetSymbolAddress(&pWh, g_Wh);
    cudaGetSymbolAddress(&pWtrT, g_WtrT);
    cudaGetSymbolAddress(&pWprT, g_WprT);

    // stage 0: all weight preps in one launch
    prep_weights<<<608, dim3(32, 8)>>>(W_cls, W_tr, W_pr, (__half*)pWh,
                                       (__half*)pWtrT, (__half*)pWprT);

    // stage 1a: YP
    {
        cudaFuncSetAttribute(yp_gemm_f16, cudaFuncAttributeMaxDynamicSharedMemorySize,
                             YP_SMEM);
        yp_gemm_f16<<<200, 128, YP_SMEM>>>(y, (const __half*)pWprT, b_pr, (float*)pYP);
    }
    // stage 1b+2: XT tile + tanh expansion -> Zh (fused; XT never hits global)
    {
        cudaFuncSetAttribute(xt_z_f16, cudaFuncAttributeMaxDynamicSharedMemorySize,
                             XT_SMEM);
        xt_z_f16<<<400, 128, XT_SMEM>>>(x, (const __half*)pWtrT, b_tr,
                                        (const float*)pYP, (__half*)pZh);
    }
    // stage 3 (persistent, frozen R13 config)
    {
        cudaFuncSetAttribute(joint_gemm_f16, cudaFuncAttributeMaxDynamicSharedMemorySize,
                             JSMEM);
        joint_gemm_f16<<<NJCTAS, 128, JSMEM>>>((const __half*)pZh, (const __half*)pWh,
                                               b_cls, out);
    }
}